// round 4
// baseline (speedup 1.0000x reference)
#include <cuda_runtime.h>
#include <cuda_fp16.h>
#include <cstdint>

// AxialAttention: 512 independent attention problems of [S=512, c=64].
// B' = outer*8 + W; q/k/v/out element (B', s, c) at outer*262144 + s*512 + W*64 + c.
// attn output [B',512,512] contiguous, placed after `out` in d_out.
// Register-resident score fragments: QK^T C-frags stay in regs, softmax via
// quad-shuffle + tiny smem reduce, P packed to half2 in regs, per-warp partial
// PV with one cross-warp O reduction. fp16 m16n8k16 MMAs.

#define QSTRH 72           // Q smem row stride (halves)
#define KSTR 72            // K smem row stride (floats)
#define VSTR 76            // V smem row stride (floats)
#define QROWS 32
#define KVBUF (64*VSTR)
#define RED_OFF (QROWS*QSTRH/2 + 2*KVBUF)
#define SMEM_FLOATS (RED_OFF + 260)
#define NEG_INF __int_as_float(0xff800000)

__device__ __forceinline__ uint32_t packh2(float a, float b) {
    __half2 h = __floats2half2_rn(a, b);
    return *reinterpret_cast<uint32_t*>(&h);
}

__device__ __forceinline__ void mma16(float* c,
        uint32_t a0, uint32_t a1, uint32_t a2, uint32_t a3,
        uint32_t b0, uint32_t b1) {
    asm volatile(
        "mma.sync.aligned.m16n8k16.row.col.f32.f16.f16.f32 "
        "{%0,%1,%2,%3},{%4,%5,%6,%7},{%8,%9},{%0,%1,%2,%3};\n"
        : "+f"(c[0]), "+f"(c[1]), "+f"(c[2]), "+f"(c[3])
        : "r"(a0), "r"(a1), "r"(a2), "r"(a3), "r"(b0), "r"(b1));
}

__device__ __forceinline__ void cp16(float* s, const float* g) {
    uint32_t sa = (uint32_t)__cvta_generic_to_shared(s);
    asm volatile("cp.async.cg.shared.global [%0], [%1], 16;\n" :: "r"(sa), "l"(g));
}
#define CP_COMMIT asm volatile("cp.async.commit_group;\n" ::: "memory")
#define CP_WAIT0  asm volatile("cp.async.wait_group 0;\n" ::: "memory")

// load a 64-row x 64-col fp32 chunk into smem
__device__ __forceinline__ void load_chunk(float* dst, const float* gb,
                                           int row0, int str, int tid) {
    #pragma unroll
    for (int i = 0; i < 4; i++) {
        int idx = tid + 256 * i;        // 1024 float4 total
        int r   = idx >> 4;
        int c4  = (idx & 15) << 2;
        cp16(dst + r * str + c4, gb + (long)(row0 + r) * 512 + c4);
    }
}

__global__ __launch_bounds__(256, 2)
void axial_attn_kernel(const float* __restrict__ q,
                       const float* __restrict__ k,
                       const float* __restrict__ v,
                       const int*   __restrict__ amask,
                       const float* __restrict__ hmask,
                       float* __restrict__ outp,
                       float* __restrict__ attnp)
{
    extern __shared__ float sm[];
    __half* Qs  = (__half*)sm;                 // QROWS x QSTRH halves
    float*  KV  = sm + QROWS * QSTRH / 2;      // 2 x KVBUF fp32
    float*  red = sm + RED_OFF;                // [2][4cg][32rows]

    const int tid  = threadIdx.x;
    const int w    = tid >> 5;
    const int lane = tid & 31;
    const int gid  = lane >> 2;
    const int tig  = lane & 3;
    const int rg   = w >> 2;
    const int cg   = w & 3;
    const int m0   = rg * 16;
    const int cb   = cg * 16 + 2 * tig;   // fragment col base within a chunk

    const int Bp    = blockIdx.y;
    const int q0    = blockIdx.x * QROWS;
    const int outer = Bp >> 3;
    const int Wd    = Bp & 7;
    const long base = (long)outer * 262144 + (long)Wd * 64;

    const float* qb = q + base;
    const float* kb = k + base;
    const float* vb = v + base;
    float* ob = outp + base;
    float* ab = attnp + (long)Bp * 262144;

    const int qlo = q0 + m0 + gid;
    const int qhi = qlo + 8;

    // kick off K chunk 0 fetch
    load_chunk(KV, kb, 0, KSTR, tid);
    CP_COMMIT;

    // ---- load Q tile (scale by 0.125, convert half) ----
    #pragma unroll
    for (int i = 0; i < 2; i++) {
        int idx = tid + 256 * i;
        int r   = idx >> 4;
        int c4  = (idx & 15) << 2;
        float4 t = *(const float4*)(qb + (long)(q0 + r) * 512 + c4);
        uint32_t h0 = packh2(t.x * 0.125f, t.y * 0.125f);
        uint32_t h1 = packh2(t.z * 0.125f, t.w * 0.125f);
        *(uint2*)(Qs + r * QSTRH + c4) = make_uint2(h0, h1);
    }
    __syncthreads();

    // ---- preload A fragments ----
    uint32_t A[4][4];
    #pragma unroll
    for (int ks = 0; ks < 4; ks++) {
        const __half* qr = Qs + (m0 + gid) * QSTRH + ks * 16 + 2 * tig;
        A[ks][0] = *(const uint32_t*)(qr);
        A[ks][1] = *(const uint32_t*)(qr + 8 * QSTRH);
        A[ks][2] = *(const uint32_t*)(qr + 8);
        A[ks][3] = *(const uint32_t*)(qr + 8 * QSTRH + 8);
    }

    // ---- QK^T: all 8 chunks accumulate into registers ----
    float C[8][2][4];
    #pragma unroll
    for (int kc = 0; kc < 8; kc++)
        #pragma unroll
        for (int nt = 0; nt < 2; nt++)
            #pragma unroll
            for (int i = 0; i < 4; i++) C[kc][nt][i] = 0.f;

    for (int kc = 0; kc < 8; kc++) {
        float* cur = KV + (kc & 1) * KVBUF;
        CP_WAIT0;
        __syncthreads();
        if (kc < 7) {
            load_chunk(KV + ((kc + 1) & 1) * KVBUF, kb, (kc + 1) * 64, KSTR, tid);
            CP_COMMIT;
        } else {
            load_chunk(KV, vb, 0, VSTR, tid);   // prefetch V0, hides under softmax
            CP_COMMIT;
        }
        #pragma unroll
        for (int nt = 0; nt < 2; nt++) {
            const float* kr = cur + (cg * 16 + nt * 8 + gid) * KSTR + 2 * tig;
            #pragma unroll
            for (int ks = 0; ks < 4; ks++) {
                float2 f0 = *(const float2*)(kr + ks * 16);
                float2 f1 = *(const float2*)(kr + ks * 16 + 8);
                mma16(C[kc][nt], A[ks][0], A[ks][1], A[ks][2], A[ks][3],
                      packh2(f0.x, f0.y), packh2(f1.x, f1.y));
            }
        }
    }

    // ---- mask + row max (regs -> quad shuffle -> cross-warp smem) ----
    const int*   mloB = amask + (long)qlo * 512;
    const int*   mhiB = amask + (long)qhi * 512;
    float mxl = NEG_INF, mxh = NEG_INF;
    #pragma unroll
    for (int kc = 0; kc < 8; kc++)
        #pragma unroll
        for (int nt = 0; nt < 2; nt++) {
            int col = kc * 64 + cb + nt * 8;
            int2 ml = *(const int2*)(mloB + col);
            int2 mh = *(const int2*)(mhiB + col);
            if (ml.x == 0) C[kc][nt][0] = NEG_INF;
            if (ml.y == 0) C[kc][nt][1] = NEG_INF;
            if (mh.x == 0) C[kc][nt][2] = NEG_INF;
            if (mh.y == 0) C[kc][nt][3] = NEG_INF;
            mxl = fmaxf(mxl, fmaxf(C[kc][nt][0], C[kc][nt][1]));
            mxh = fmaxf(mxh, fmaxf(C[kc][nt][2], C[kc][nt][3]));
        }
    mxl = fmaxf(mxl, __shfl_xor_sync(0xFFFFFFFFu, mxl, 1));
    mxl = fmaxf(mxl, __shfl_xor_sync(0xFFFFFFFFu, mxl, 2));
    mxh = fmaxf(mxh, __shfl_xor_sync(0xFFFFFFFFu, mxh, 1));
    mxh = fmaxf(mxh, __shfl_xor_sync(0xFFFFFFFFu, mxh, 2));
    if (tig == 0) {
        red[cg * 32 + m0 + gid]     = mxl;
        red[cg * 32 + m0 + gid + 8] = mxh;
    }
    __syncthreads();
    float gml = fmaxf(fmaxf(red[0 * 32 + m0 + gid], red[1 * 32 + m0 + gid]),
                      fmaxf(red[2 * 32 + m0 + gid], red[3 * 32 + m0 + gid]));
    float gmh = fmaxf(fmaxf(red[0 * 32 + m0 + gid + 8], red[1 * 32 + m0 + gid + 8]),
                      fmaxf(red[2 * 32 + m0 + gid + 8], red[3 * 32 + m0 + gid + 8]));

    // ---- exp + row sum ----
    float sl = 0.f, sh = 0.f;
    #pragma unroll
    for (int kc = 0; kc < 8; kc++)
        #pragma unroll
        for (int nt = 0; nt < 2; nt++) {
            float e0 = __expf(C[kc][nt][0] - gml);
            float e1 = __expf(C[kc][nt][1] - gml);
            float e2 = __expf(C[kc][nt][2] - gmh);
            float e3 = __expf(C[kc][nt][3] - gmh);
            C[kc][nt][0] = e0; C[kc][nt][1] = e1;
            C[kc][nt][2] = e2; C[kc][nt][3] = e3;
            sl += e0 + e1;
            sh += e2 + e3;
        }
    sl += __shfl_xor_sync(0xFFFFFFFFu, sl, 1);
    sl += __shfl_xor_sync(0xFFFFFFFFu, sl, 2);
    sh += __shfl_xor_sync(0xFFFFFFFFu, sh, 1);
    sh += __shfl_xor_sync(0xFFFFFFFFu, sh, 2);
    if (tig == 0) {
        red[128 + cg * 32 + m0 + gid]     = sl;
        red[128 + cg * 32 + m0 + gid + 8] = sh;
    }
    __syncthreads();
    float invl = 1.0f / (red[128 + 0 * 32 + m0 + gid] + red[128 + 1 * 32 + m0 + gid] +
                         red[128 + 2 * 32 + m0 + gid] + red[128 + 3 * 32 + m0 + gid]);
    float invh = 1.0f / (red[128 + 0 * 32 + m0 + gid + 8] + red[128 + 1 * 32 + m0 + gid + 8] +
                         red[128 + 2 * 32 + m0 + gid + 8] + red[128 + 3 * 32 + m0 + gid + 8]);

    // ---- head_mask, write attn from fragments, pack P (half2) in regs ----
    const float* hloB = hmask + (long)qlo * 512;
    const float* hhiB = hmask + (long)qhi * 512;
    float* aloB = ab + (long)qlo * 512;
    float* ahiB = ab + (long)qhi * 512;
    uint32_t P[8][2][2];
    #pragma unroll
    for (int kc = 0; kc < 8; kc++)
        #pragma unroll
        for (int nt = 0; nt < 2; nt++) {
            int col = kc * 64 + cb + nt * 8;
            float2 hl = *(const float2*)(hloB + col);
            float2 hh = *(const float2*)(hhiB + col);
            float a0 = C[kc][nt][0] * invl * hl.x;
            float a1 = C[kc][nt][1] * invl * hl.y;
            float a2 = C[kc][nt][2] * invh * hh.x;
            float a3 = C[kc][nt][3] * invh * hh.y;
            *(float2*)(aloB + col) = make_float2(a0, a1);
            *(float2*)(ahiB + col) = make_float2(a2, a3);
            P[kc][nt][0] = packh2(a0, a1);
            P[kc][nt][1] = packh2(a2, a3);
        }

    // ---- PV: per-warp partial O over its k-slices ----
    float O[8][4];
    #pragma unroll
    for (int nt = 0; nt < 8; nt++)
        #pragma unroll
        for (int i = 0; i < 4; i++) O[nt][i] = 0.f;

    for (int vc = 0; vc < 8; vc++) {
        float* cur = KV + (vc & 1) * KVBUF;
        CP_WAIT0;
        __syncthreads();
        if (vc < 7) {
            load_chunk(KV + ((vc + 1) & 1) * KVBUF, vb, (vc + 1) * 64, VSTR, tid);
            CP_COMMIT;
        }
        uint32_t a0 = P[vc][0][0], a1 = P[vc][0][1];
        uint32_t a2 = P[vc][1][0], a3 = P[vc][1][1];
        const float* vrb = cur + (cg * 16 + 2 * tig) * VSTR + gid;
        #pragma unroll
        for (int nt = 0; nt < 8; nt++) {
            uint32_t b0 = packh2(vrb[nt * 8],            vrb[VSTR + nt * 8]);
            uint32_t b1 = packh2(vrb[8 * VSTR + nt * 8], vrb[9 * VSTR + nt * 8]);
            mma16(O[nt], a0, a1, a2, a3, b0, b1);
        }
    }

    // ---- cross-warp O reduction (4 cg partials) in freed KV smem ----
    __syncthreads();
    float* Op = KV;   // 4 regions of 32 x 68
    #pragma unroll
    for (int nt = 0; nt < 8; nt++) {
        float* p0 = Op + cg * 2176 + (m0 + gid) * 68 + nt * 8 + 2 * tig;
        *(float2*)(p0)            = make_float2(O[nt][0], O[nt][1]);
        *(float2*)(p0 + 8 * 68)   = make_float2(O[nt][2], O[nt][3]);
    }
    __syncthreads();
    #pragma unroll
    for (int i = 0; i < 4; i++) {
        int e    = tid + 256 * i;      // 1024 float2 elements
        int row  = e >> 5;
        int cf2  = (e & 31) * 2;
        float2 s = *(const float2*)(Op + 0 * 2176 + row * 68 + cf2);
        float2 t1 = *(const float2*)(Op + 1 * 2176 + row * 68 + cf2);
        float2 t2 = *(const float2*)(Op + 2 * 2176 + row * 68 + cf2);
        float2 t3 = *(const float2*)(Op + 3 * 2176 + row * 68 + cf2);
        s.x += t1.x + t2.x + t3.x;
        s.y += t1.y + t2.y + t3.y;
        *(float2*)(ob + (long)(q0 + row) * 512 + cf2) = s;
    }
}

extern "C" void kernel_launch(void* const* d_in, const int* in_sizes, int n_in,
                              void* d_out, int out_size) {
    const float* q  = (const float*)d_in[0];
    const float* k  = (const float*)d_in[1];
    const float* v  = (const float*)d_in[2];
    const int*   am = (const int*)d_in[3];
    const float* hm = (const float*)d_in[4];

    float* out  = (float*)d_out;
    float* attn = out + (long)in_sizes[0];

    size_t smem = (size_t)SMEM_FLOATS * sizeof(float);
    cudaFuncSetAttribute(axial_attn_kernel,
                         cudaFuncAttributeMaxDynamicSharedMemorySize, (int)smem);

    dim3 grid(16, 512);   // x: 32-row query tiles, y: flattened batch B'
    axial_attn_kernel<<<grid, 256, smem>>>(q, k, v, am, hm, out, attn);
}